// round 15
// baseline (speedup 1.0000x reference)
#include <cuda_runtime.h>
#include <cuda_bf16.h>
#include <cuda_fp16.h>
#include <math.h>
#include <stdint.h>

typedef unsigned long long ull;

#define Bn 8
#define Cn 64
#define HWn 4096
#define LOG2E 1.4426950408889634f

// ---------------- scratch (device globals; no allocs allowed) ----------------
__device__ __align__(16) float d_psi[Bn*Cn*HWn];     // 8MB
__device__ __align__(16) float d_fb [Bn*8*HWn];      // pre-scaled by log2(e)
__device__ __align__(16) char  d_fc2[Bn*64*3072];    // 1.5MB fp16 tile-major: [b][jt][j*48 + k*2] (k-pad zeroed)
__device__ __align__(16) char  d_fd2[Bn*64*8192];    // 4MB fp16, tile-major SWZ: [b][jt][SWZ(c*128+jp*4)]
__device__ __align__(16) float d_att[Bn*64*64];      // CAM gram (atomic-accumulated)
__device__ __align__(16) __nv_bfloat16 d_Wh[512*64]; // folded weight hi, [cin][out]
__device__ __align__(16) __nv_bfloat16 d_Wl[512*64]; // folded weight lo
__device__ __align__(16) float d_bias[64];
__device__ __align__(16) float d_wp[64];
__device__ __align__(16) float d_bp[1];

// ---------------- f32x2 helpers ----------------
__device__ __forceinline__ ull pk2(float lo, float hi) {
    ull r; asm("mov.b64 %0, {%1, %2};" : "=l"(r) : "f"(lo), "f"(hi)); return r;
}
__device__ __forceinline__ void upk2(ull v, float& lo, float& hi) {
    asm("mov.b64 {%0, %1}, %2;" : "=f"(lo), "=f"(hi) : "l"(v));
}
__device__ __forceinline__ ull ffma2(ull a, ull b, ull c) {
    ull d; asm("fma.rn.f32x2 %0, %1, %2, %3;" : "=l"(d) : "l"(a), "l"(b), "l"(c)); return d;
}
__device__ __forceinline__ float ex2f(float x) {
    float r; asm("ex2.approx.f32 %0, %1;" : "=f"(r) : "f"(x)); return r;
}

// ---------------- warp MMA helpers ----------------
__device__ __forceinline__ uint32_t smem_u32(const void* p) {
    uint32_t a;
    asm("{ .reg .u64 t; cvta.to.shared.u64 t, %1; cvt.u32.u64 %0, t; }" : "=r"(a) : "l"(p));
    return a;
}
#define SWZ(off) ((off) ^ (((off) >> 3) & 0x70))
__device__ __forceinline__ void ldsm_x4(uint32_t& r0, uint32_t& r1, uint32_t& r2, uint32_t& r3,
                                        uint32_t addr) {
    asm volatile("ldmatrix.sync.aligned.m8n8.x4.shared.b16 {%0,%1,%2,%3}, [%4];"
                 : "=r"(r0), "=r"(r1), "=r"(r2), "=r"(r3) : "r"(addr));
}
__device__ __forceinline__ void ldsm_x4t(uint32_t& r0, uint32_t& r1, uint32_t& r2, uint32_t& r3,
                                         uint32_t addr) {
    asm volatile("ldmatrix.sync.aligned.m8n8.x4.trans.shared.b16 {%0,%1,%2,%3}, [%4];"
                 : "=r"(r0), "=r"(r1), "=r"(r2), "=r"(r3) : "r"(addr));
}
__device__ __forceinline__ void mma_bf16(float* d, const uint32_t* a, const uint32_t* b) {
    asm volatile(
        "mma.sync.aligned.m16n8k16.row.col.f32.bf16.bf16.f32 "
        "{%0,%1,%2,%3}, {%4,%5,%6,%7}, {%8,%9}, {%0,%1,%2,%3};"
        : "+f"(d[0]), "+f"(d[1]), "+f"(d[2]), "+f"(d[3])
        : "r"(a[0]), "r"(a[1]), "r"(a[2]), "r"(a[3]), "r"(b[0]), "r"(b[1]));
}
__device__ __forceinline__ void mma_f16s(float* d, const uint32_t* a, uint32_t b0, uint32_t b1) {
    asm volatile(
        "mma.sync.aligned.m16n8k16.row.col.f32.f16.f16.f32 "
        "{%0,%1,%2,%3}, {%4,%5,%6,%7}, {%8,%9}, {%0,%1,%2,%3};"
        : "+f"(d[0]), "+f"(d[1]), "+f"(d[2]), "+f"(d[3])
        : "r"(a[0]), "r"(a[1]), "r"(a[2]), "r"(a[3]), "r"(b0), "r"(b1));
}
__device__ __forceinline__ uint32_t cvt_bf16x2(float a, float b) {
    uint32_t r;
    asm("cvt.rn.satfinite.bf16x2.f32 %0, %1, %2;" : "=r"(r) : "f"(b), "f"(a));
    return r;
}
__device__ __forceinline__ uint32_t cvt_f16x2(float a, float b) {
    // lower half = a, upper = b
    uint32_t r;
    asm("cvt.rn.f16x2.f32 %0, %1, %2;" : "=r"(r) : "f"(b), "f"(a));
    return r;
}
__device__ __forceinline__ uint32_t ex2h2(uint32_t a) {
    uint32_t r;
    asm("ex2.approx.f16x2 %0, %1;" : "=r"(r) : "r"(a));
    return r;
}
__device__ __forceinline__ uint32_t hadd2u(uint32_t a, uint32_t b) {
    uint32_t r;
    asm("add.rn.f16x2 %0, %1, %2;" : "=r"(r) : "r"(a), "r"(b));
    return r;
}

// ---------------- prep: coalesced stores + smem-cached BN factors ----------------
__global__ void __launch_bounds__(256) k_prep(
                       const float* Wg_w, const float* Wg_b, const float* gg, const float* gb,
                       const float* gm, const float* gv,
                       const float* Wx_w, const float* Wx_b, const float* xg, const float* xb,
                       const float* xm, const float* xv,
                       const float* psi_w, const float* psi_b, const float* pg, const float* pbt,
                       const float* pm, const float* pv) {
    __shared__ float invs[128];
    int t = threadIdx.x;
    if (t < 64)       invs[t] = gg[t] * rsqrtf(gv[t] + 1e-5f);
    else if (t < 128) invs[t] = xg[t-64] * rsqrtf(xv[t-64] + 1e-5f);
    __syncthreads();
    int r = blockIdx.x*4 + (t >> 6);
    int o = t & 63;
    int set = r >> 8;
    int cin = r & 255;
    const float* Ww = set ? Wx_w : Wg_w;
    float v = Ww[o*256 + cin] * invs[set*64 + o];
    __nv_bfloat16 h = __float2bfloat16(v);
    d_Wh[r*64 + o] = h;
    d_Wl[r*64 + o] = __float2bfloat16(v - __bfloat162float(h));
    d_att[blockIdx.x*256 + t] = 0.f;
    if (r == 0) {
        d_bias[o] = (Wg_b[o] - gm[o]) * invs[o] + gb[o]
                  + (Wx_b[o] - xm[o]) * invs[64 + o] + xb[o];
        float invp = pg[0] * rsqrtf(pv[0] + 1e-5f);
        d_wp[o] = psi_w[o] * invp;
        if (o == 0) d_bp[0] = (psi_b[0] - pm[0]) * invp + pbt[0];
    }
}

// ---------------- psi via bf16-split HMMA + fused fb/fc/fd convs + CAM gram ----------------
// Mainloop (R13 staged form): A_hi 0..16384 | A_lo ..32768 | W_hi ..40960 | W_lo ..49152
//                             f32stage 49152..81920 | bias 81920..82176
// Epilogue union: psi_t [64][129] f 0..33024 | cw_s 33024..53504 | cbias 53504..53824 | fds 54272..70656
__global__ void __launch_bounds__(256) k_psi2(const float* __restrict__ g, const float* __restrict__ x,
                                              const float* __restrict__ pb_w, const float* __restrict__ pb_b,
                                              const float* __restrict__ pc_w, const float* __restrict__ pc_b,
                                              const float* __restrict__ pd_w, const float* __restrict__ pd_b) {
    extern __shared__ __align__(1024) char ps[];
    uint32_t base = smem_u32(ps);
    uint32_t ahi = base, whi = base + 32768;
    float* f32s   = (float*)(ps + 49152);
    float* bias_s = (float*)(ps + 81920);
    float* psi_t  = (float*)ps;
    float* cw_s   = (float*)(ps + 33024);
    float* cbias  = (float*)(ps + 53504);
    char*  fds    = ps + 54272;

    int b = blockIdx.y, p0 = blockIdx.x*128, t = threadIdx.x;
    int w = t >> 5, lane = t & 31;
    if (t < 64) bias_s[t] = d_bias[t];

    float dfr[8][4];
#pragma unroll
    for (int nf = 0; nf < 8; nf++)
#pragma unroll
        for (int q = 0; q < 4; q++) dfr[nf][q] = 0.f;

    int r7 = lane & 7;
    int hsel = lane >> 4;
    uint32_t a_row = ahi + (uint32_t)(w*16 + (lane & 15))*128;
    uint32_t b_row = whi + (uint32_t)((((lane >> 3) & 1)*8 + r7))*128;

    for (int cb = 0; cb < 8; cb++) {
        __syncthreads();
        {
            const float* src = (cb < 4) ? g + ((size_t)b*256 + cb*64)*HWn
                                        : x + ((size_t)b*256 + (cb-4)*64)*HWn;
#pragma unroll
            for (int i = 0; i < 8; i++) {
                int idx = t + i*256;
                int c = idx >> 5, p4 = idx & 31;
                float4 v = *(const float4*)&src[(size_t)c*HWn + p0 + p4*4];
                *(float4*)&f32s[c*128 + p4*4] = v;
            }
        }
        {
#pragma unroll
            for (int q = 0; q < 2; q++) {
                int qi = t + q*256;
                int row = qi >> 3, qq = qi & 7;
                uint32_t so = SWZ((uint32_t)(row*128 + qq*16));
                *(uint4*)(ps + 32768 + so) =
                    *(const uint4*)((const char*)d_Wh + (size_t)(cb*64+row)*128 + qq*16);
                *(uint4*)(ps + 40960 + so) =
                    *(const uint4*)((const char*)d_Wl + (size_t)(cb*64+row)*128 + qq*16);
            }
        }
        __syncthreads();
        {
            int p = t & 127, half = t >> 7;
#pragma unroll
            for (int oct = 0; oct < 4; oct++) {
                int c0 = half*32 + oct*8;
                float v[8];
#pragma unroll
                for (int j = 0; j < 8; j++) v[j] = f32s[(c0+j)*128 + p];
                uint32_t uh[4], ul[4];
#pragma unroll
                for (int j = 0; j < 4; j++) {
                    uint32_t h = cvt_bf16x2(v[2*j], v[2*j+1]);
                    float h0 = __uint_as_float(h << 16);
                    float h1 = __uint_as_float(h & 0xffff0000u);
                    uh[j] = h;
                    ul[j] = cvt_bf16x2(v[2*j] - h0, v[2*j+1] - h1);
                }
                uint32_t so = SWZ((uint32_t)(p*128 + c0*2));
                *(uint4*)(ps + so)         = make_uint4(uh[0], uh[1], uh[2], uh[3]);
                *(uint4*)(ps + 16384 + so) = make_uint4(ul[0], ul[1], ul[2], ul[3]);
            }
        }
        __syncthreads();
        uint32_t afh[4][4], afl[4][4];
#pragma unroll
        for (int ks = 0; ks < 4; ks++) {
            uint32_t aq = (uint32_t)(((2*ks + hsel) ^ r7) * 16);
            ldsm_x4(afh[ks][0], afh[ks][1], afh[ks][2], afh[ks][3], a_row + aq);
            ldsm_x4(afl[ks][0], afl[ks][1], afl[ks][2], afl[ks][3], a_row + 16384 + aq);
        }
#pragma unroll
        for (int ks = 0; ks < 4; ks++) {
#pragma unroll
            for (int nn = 0; nn < 4; nn++) {
                uint32_t bq = (uint32_t)(((2*nn + hsel) ^ r7) * 16);
                uint32_t baddr = b_row + ks*2048 + bq;
                uint32_t bh[4], bl[4];
                ldsm_x4t(bh[0], bh[1], bh[2], bh[3], baddr);
                ldsm_x4t(bl[0], bl[1], bl[2], bl[3], baddr + 8192);
                mma_bf16(dfr[2*nn],   afh[ks], bh);
                mma_bf16(dfr[2*nn],   afh[ks], bl);
                mma_bf16(dfr[2*nn],   afl[ks], bh);
                mma_bf16(dfr[2*nn+1], afh[ks], bh + 2);
                mma_bf16(dfr[2*nn+1], afh[ks], bl + 2);
                mma_bf16(dfr[2*nn+1], afl[ks], bh + 2);
            }
        }
    }
    __syncthreads();
    // ---- epilogue 1: fragments -> psi_t [c][129], stage conv weights ----
    {
        int gr = lane >> 2, tc = lane & 3;
        int i1 = w*16 + gr, i2 = i1 + 8;
#pragma unroll
        for (int nf = 0; nf < 8; nf++) {
            int c0 = nf*8 + 2*tc;
            float b0 = bias_s[c0], b1 = bias_s[c0+1];
            psi_t[c0*129 + i1]     = fmaxf(dfr[nf][0] + b0, 0.f);
            psi_t[(c0+1)*129 + i1] = fmaxf(dfr[nf][1] + b1, 0.f);
            psi_t[c0*129 + i2]     = fmaxf(dfr[nf][2] + b0, 0.f);
            psi_t[(c0+1)*129 + i2] = fmaxf(dfr[nf][3] + b1, 0.f);
        }
    }
    for (int idx = t; idx < 5120; idx += 256) {
        int c = idx / 80, o = idx % 80;
        float wv;
        if (o < 8)       wv = pb_w[o*64 + c];
        else if (o < 16) wv = pc_w[(o-8)*64 + c];
        else             wv = pd_w[(o-16)*64 + c];
        cw_s[idx] = wv;
    }
    if (t < 80) cbias[t] = (t < 8) ? pb_b[t] : (t < 16 ? pc_b[t-8] : pd_b[t-16]);
    __syncthreads();
    // ---- epilogue 2: store psi, fb conv; fc -> d_fc2 tiles; fd -> swizzled smem ----
    for (int idx = t; idx < 8192; idx += 256) {
        int c = idx >> 7, p = idx & 127;
        d_psi[((size_t)b*Cn + c)*HWn + p0 + p] = psi_t[c*129 + p];
    }
    {
        int pos = t & 127, half = t >> 7;
        int o0 = half*40;
        int tt = pos >> 6, jp = pos & 63;
        uint32_t fbase = (uint32_t)(tt*8192 + (jp & 1)*2);
        uint32_t fslot = (uint32_t)((jp >> 1)*4);
        ull acc[20];
#pragma unroll
        for (int q = 0; q < 20; q++) acc[q] = pk2(cbias[o0 + 2*q], cbias[o0 + 2*q + 1]);
        for (int c = 0; c < 64; c++) {
            float v = psi_t[c*129 + pos];
            ull v2 = pk2(v, v);
            const ull* wr = (const ull*)&cw_s[c*80 + o0];
#pragma unroll
            for (int q = 0; q < 20; q++) acc[q] = ffma2(v2, wr[q], acc[q]);
        }
        float fcv[8];
#pragma unroll
        for (int q = 0; q < 20; q++) {
            float v0, v1; upk2(acc[q], v0, v1);
            int o = o0 + 2*q;
#pragma unroll
            for (int s = 0; s < 2; s++) {
                float v = s ? v1 : v0;
                int oo = o + s;
                if (oo < 8)       d_fb[((size_t)b*8 + oo)*HWn + p0 + pos] = v * LOG2E;
                else if (oo < 16) { if (half == 0) fcv[oo - 8] = v; }
                else {
                    int c = oo - 16;
                    *(__half*)(fds + fbase + SWZ((uint32_t)(c*128) + fslot)) = __float2half(v);
                }
            }
        }
        // fc tile write: fp16 k0-7 at row j*48, zero pad at +16
        if (half == 0) {
            int gj = p0 + pos;
            char* dst = d_fc2 + ((size_t)b*64 + (gj >> 6))*3072 + (gj & 63)*48;
            *(uint4*)dst = make_uint4(cvt_f16x2(fcv[0], fcv[1]), cvt_f16x2(fcv[2], fcv[3]),
                                      cvt_f16x2(fcv[4], fcv[5]), cvt_f16x2(fcv[6], fcv[7]));
            *(uint4*)(dst + 16) = make_uint4(0u, 0u, 0u, 0u);
        }
    }
    __syncthreads();
    // ---- copy fd tiles to global (coalesced uint4) ----
    {
        char* fdst = d_fd2 + (size_t)b*524288 + (size_t)(blockIdx.x*2)*8192;
#pragma unroll
        for (int k = 0; k < 4; k++) {
            int idx = t + k*256;
            *(uint4*)(fdst + idx*16) = *(const uint4*)(fds + idx*16);
        }
    }
    // ---- CAM gram atomics ----
    {
        int cjg = t & 15, cig = t >> 4;
        float ga[4][4];
#pragma unroll
        for (int r = 0; r < 4; r++)
#pragma unroll
            for (int q = 0; q < 4; q++) ga[r][q] = 0.f;
        for (int p = 0; p < 128; p++) {
            float a0 = psi_t[(cig*4+0)*129 + p];
            float a1 = psi_t[(cig*4+1)*129 + p];
            float a2 = psi_t[(cig*4+2)*129 + p];
            float a3 = psi_t[(cig*4+3)*129 + p];
            float b0 = psi_t[(cjg*4+0)*129 + p];
            float b1 = psi_t[(cjg*4+1)*129 + p];
            float b2 = psi_t[(cjg*4+2)*129 + p];
            float b3 = psi_t[(cjg*4+3)*129 + p];
            ga[0][0]+=a0*b0; ga[0][1]+=a0*b1; ga[0][2]+=a0*b2; ga[0][3]+=a0*b3;
            ga[1][0]+=a1*b0; ga[1][1]+=a1*b1; ga[1][2]+=a1*b2; ga[1][3]+=a1*b3;
            ga[2][0]+=a2*b0; ga[2][1]+=a2*b1; ga[2][2]+=a2*b2; ga[2][3]+=a2*b3;
            ga[3][0]+=a3*b0; ga[3][1]+=a3*b1; ga[3][2]+=a3*b2; ga[3][3]+=a3*b3;
        }
#pragma unroll
        for (int r = 0; r < 4; r++)
#pragma unroll
            for (int q = 0; q < 4; q++)
                atomicAdd(&d_att[(b*64 + cig*4 + r)*64 + cjg*4 + q], ga[r][q]);
    }
}

// ---------------- PAM + CAM softmax + gate + final multiply ----------------
__global__ void __launch_bounds__(256, 2) k_pam3(const float* __restrict__ alpha_p,
                                                 const float* __restrict__ beta_p,
                                                 const float* __restrict__ x,
                                                 float* __restrict__ out) {
    extern __shared__ __align__(1024) char dsm[];
    float* psi_s = (float*)dsm;               // 64*132 f      0..33792
    float* pam_s = (float*)(dsm + 33792);     // 64*132 f      ..67584
    float* W2_s  = (float*)(dsm + 67584);     // 64*66 f       ..84480
    float* wp_s  = (float*)(dsm + 84480);     // 64 f          ..84736
    float* gred  = (float*)(dsm + 84736);     // 256 f         ..85760
    float* z_s   = (float*)(dsm + 85760);     // 128 f         ..86272
    float* att_s = (float*)(dsm + 86272);     // 64*65 f       ..102912

    uint32_t sbase = smem_u32(dsm);
    uint32_t fbb   = sbase + 16384;
    uint32_t fcb   = sbase + 22528;

    int b = blockIdx.y, I0 = blockIdx.x*128, t = threadIdx.x;
    int w = t >> 5, lane = t & 31;
    int gr = lane >> 2, tc = lane & 3;
    int i1 = w*16 + gr, i2 = i1 + 8;

    // zero fb k8-15 pad (fc pad comes baked into d_fc2 tiles)
    for (int idx = t; idx < 512; idx += 256)
        *(uint32_t*)(dsm + 16384 + (idx>>2)*48 + 16 + (idx&3)*4) = 0u;
    {
        int i = t & 127, half = t >> 7;
        float v0 = d_fb[((size_t)b*8 + half*4 + 0)*HWn + I0 + i];
        float v1 = d_fb[((size_t)b*8 + half*4 + 1)*HWn + I0 + i];
        float v2 = d_fb[((size_t)b*8 + half*4 + 2)*HWn + I0 + i];
        float v3 = d_fb[((size_t)b*8 + half*4 + 3)*HWn + I0 + i];
        *(uint32_t*)(dsm + 16384 + i*48 + half*8)     = cvt_f16x2(v0, v1);
        *(uint32_t*)(dsm + 16384 + i*48 + half*8 + 4) = cvt_f16x2(v2, v3);
    }
    __syncthreads();

    uint32_t af[4];
    {
        uint32_t aaddr = fbb + (uint32_t)(w*16 + (lane & 15))*48 + (lane >> 4)*16;
        ldsm_x4(af[0], af[1], af[2], af[3], aaddr);
    }

    float acc[8][4];
#pragma unroll
    for (int ng = 0; ng < 8; ng++)
#pragma unroll
        for (int q = 0; q < 4; q++) acc[ng][q] = 0.f;
    float z1 = 0.f, z2 = 0.f;
    float m1 = -1e30f, m2 = -1e30f;

    const char* fdg = d_fd2 + (size_t)b*524288;
    const char* fcg = d_fc2 + (size_t)b*196608;
    uint4 fcu, fdr0, fdr1;
    {
        if (t < 192) fcu = *(const uint4*)(fcg + t*16);
        fdr0 = *(const uint4*)(fdg + t*16);
        fdr1 = *(const uint4*)(fdg + 4096 + t*16);
    }

    uint32_t fdrow = (uint32_t)(lane & 15)*128 + (uint32_t)(lane >> 4)*16;

    for (int jt = 0; jt < 64; jt++) {
        uint32_t buf = (uint32_t)(jt & 1);
        if (t < 192) *(uint4*)(dsm + 22528 + buf*3072 + t*16) = fcu;
        *(uint4*)(dsm + buf*8192 + t*16)        = fdr0;
        *(uint4*)(dsm + buf*8192 + 4096 + t*16) = fdr1;
        __syncthreads();
        if (jt < 63) {
            if (t < 192) fcu = *(const uint4*)(fcg + (size_t)(jt+1)*3072 + t*16);
            fdr0 = *(const uint4*)(fdg + (size_t)(jt+1)*8192 + t*16);
            fdr1 = *(const uint4*)(fdg + (size_t)(jt+1)*8192 + 4096 + t*16);
        }
        // energy mma (fp16 single product)
        float e[8][4];
#pragma unroll
        for (int ng = 0; ng < 8; ng++)
#pragma unroll
            for (int q = 0; q < 4; q++) e[ng][q] = 0.f;
#pragma unroll
        for (int jg = 0; jg < 4; jg++) {
            uint32_t baddr = fcb + buf*3072 + (uint32_t)(jg*16 + (lane & 15))*48 + (lane >> 4)*16;
            uint32_t bh[4];
            ldsm_x4(bh[0], bh[1], bh[2], bh[3], baddr);
            mma_f16s(e[2*jg],   af, bh[0], bh[2]);
            mma_f16s(e[2*jg+1], af, bh[1], bh[3]);
        }
        // online row max (quad shfl); rescale only when some row max moved
        float tm1 = -1e30f, tm2 = -1e30f;
#pragma unroll
        for (int ng = 0; ng < 8; ng++) {
            tm1 = fmaxf(tm1, fmaxf(e[ng][0], e[ng][1]));
            tm2 = fmaxf(tm2, fmaxf(e[ng][2], e[ng][3]));
        }
        tm1 = fmaxf(tm1, __shfl_xor_sync(0xffffffffu, tm1, 1));
        tm1 = fmaxf(tm1, __shfl_xor_sync(0xffffffffu, tm1, 2));
        tm2 = fmaxf(tm2, __shfl_xor_sync(0xffffffffu, tm2, 1));
        tm2 = fmaxf(tm2, __shfl_xor_sync(0xffffffffu, tm2, 2));
        float mn1 = fmaxf(m1, tm1), mn2 = fmaxf(m2, tm2);
        if (__any_sync(0xffffffffu, (mn1 > m1) || (mn2 > m2))) {
            float sc1 = ex2f(m1 - mn1), sc2 = ex2f(m2 - mn2);
            m1 = mn1; m2 = mn2;
            z1 *= sc1; z2 *= sc2;
#pragma unroll
            for (int ng = 0; ng < 8; ng++) {
                acc[ng][0] *= sc1; acc[ng][1] *= sc1;
                acc[ng][2] *= sc2; acc[ng][3] *= sc2;
            }
        }
        // exp via ex2.f16x2 -> p fragments
        uint32_t afr[4][4];
#pragma unroll
        for (int ng = 0; ng < 8; ng++) {
            uint32_t a01 = cvt_f16x2(e[ng][0] - m1, e[ng][1] - m1);
            uint32_t a23 = cvt_f16x2(e[ng][2] - m2, e[ng][3] - m2);
            uint32_t p01 = ex2h2(a01);
            uint32_t p23 = ex2h2(a23);
            int kp = ng >> 1;
            if ((ng & 1) == 0) { afr[kp][0] = p01; afr[kp][1] = p23; }
            else               { afr[kp][2] = p01; afr[kp][3] = p23; }
        }
        // z partial via HADD2 tree
        {
            uint32_t s1 = hadd2u(hadd2u(hadd2u(afr[0][0], afr[0][2]), hadd2u(afr[1][0], afr[1][2])),
                                 hadd2u(hadd2u(afr[2][0], afr[2][2]), hadd2u(afr[3][0], afr[3][2])));
            uint32_t s2 = hadd2u(hadd2u(hadd2u(afr[0][1], afr[0][3]), hadd2u(afr[1][1], afr[1][3])),
                                 hadd2u(hadd2u(afr[2][1], afr[2][3]), hadd2u(afr[3][1], afr[3][3])));
            float2 f1 = __half22float2(*(__half2*)&s1);
            float2 f2 = __half22float2(*(__half2*)&s2);
            z1 += f1.x + f1.y;
            z2 += f2.x + f2.y;
        }
        // accumulate mma (fp16)
#pragma unroll
        for (int ng2 = 0; ng2 < 4; ng2++) {
#pragma unroll
            for (int kp = 0; kp < 4; kp++) {
                uint32_t off = fdrow + (uint32_t)(ng2*2048 + kp*32);
                uint32_t f4[4];
                ldsm_x4(f4[0], f4[1], f4[2], f4[3], sbase + buf*8192 + SWZ(off));
                mma_f16s(acc[2*ng2],   afr[kp], f4[0], f4[2]);
                mma_f16s(acc[2*ng2+1], afr[kp], f4[1], f4[3]);
            }
        }
    }
    // ---- z reduction across the quad ----
    z1 += __shfl_xor_sync(0xffffffffu, z1, 1);
    z1 += __shfl_xor_sync(0xffffffffu, z1, 2);
    z2 += __shfl_xor_sync(0xffffffffu, z2, 1);
    z2 += __shfl_xor_sync(0xffffffffu, z2, 2);
    if (tc == 0) {
        z_s[i1] = alpha_p[0] / z1;
        z_s[i2] = alpha_p[0] / z2;
    }
    __syncthreads();
    // ---- load psi tile / att / wp ----
    for (int idx = t; idx < 8192; idx += 256) {
        int c = idx >> 7, p = idx & 127;
        psi_s[c*132 + p] = d_psi[((size_t)b*Cn + c)*HWn + I0 + p];
    }
    for (int idx = t; idx < 4096; idx += 256)
        att_s[(idx >> 6)*65 + (idx & 63)] = d_att[b*4096 + idx];
    if (t < 64) wp_s[t] = d_wp[t];
    __syncthreads();
    // ---- CAM softmax -> W2_s[c][66] (4 threads per row) ----
    {
        int r = t >> 2, q4 = t & 3;
        float v[16];
#pragma unroll
        for (int k = 0; k < 16; k++) v[k] = att_s[r*65 + q4*16 + k];
        float mx = -1e30f, mn = 1e30f;
#pragma unroll
        for (int k = 0; k < 16; k++) { mx = fmaxf(mx, v[k]); mn = fminf(mn, v[k]); }
        mx = fmaxf(mx, __shfl_xor_sync(0xffffffffu, mx, 1));
        mx = fmaxf(mx, __shfl_xor_sync(0xffffffffu, mx, 2));
        mn = fminf(mn, __shfl_xor_sync(0xffffffffu, mn, 1));
        mn = fminf(mn, __shfl_xor_sync(0xffffffffu, mn, 2));
        float m2r = mx - mn;
        float ssum = 0.f;
#pragma unroll
        for (int k = 0; k < 16; k++) { float ev = __expf((mx - v[k]) - m2r); v[k] = ev; ssum += ev; }
        ssum += __shfl_xor_sync(0xffffffffu, ssum, 1);
        ssum += __shfl_xor_sync(0xffffffffu, ssum, 2);
        float scale = beta_p[0] * wp_s[r] / ssum;
#pragma unroll
        for (int k = 0; k < 16; k++) W2_s[r*66 + q4*16 + k] = v[k] * scale;
    }
    // ---- fragments -> pam_s[c][i] ----
    {
        float zz1 = z_s[i1], zz2 = z_s[i2];
#pragma unroll
        for (int ng = 0; ng < 8; ng++) {
            int c = ng*8 + 2*tc;
            pam_s[c*132 + i1]     = acc[ng][0]*zz1 + psi_s[c*132 + i1];
            pam_s[(c+1)*132 + i1] = acc[ng][1]*zz1 + psi_s[(c+1)*132 + i1];
            pam_s[c*132 + i2]     = acc[ng][2]*zz2 + psi_s[c*132 + i2];
            pam_s[(c+1)*132 + i2] = acc[ng][3]*zz2 + psi_s[(c+1)*132 + i2];
        }
    }
    __syncthreads();
    // ---- fused CAM + gate ----
    {
        int p = t & 127, half = t >> 7;
        int c0 = half*32, d0 = half*32;
        float part1 = 0.f;
#pragma unroll 8
        for (int c = 0; c < 32; c++) {
            int cc = c0 + c;
            part1 += wp_s[cc] * psi_s[cc*132 + p] * pam_s[cc*132 + p];
        }
        ull v[16];
#pragma unroll
        for (int q = 0; q < 16; q++) v[q] = 0ull;
        for (int c = 0; c < 64; c++) {
            float pm = pam_s[c*132 + p];
            ull pm2 = pk2(pm, pm);
            const ull* wr = (const ull*)&W2_s[c*66 + d0];
#pragma unroll
            for (int q = 0; q < 16; q++) v[q] = ffma2(pm2, wr[q], v[q]);
        }
        float part2 = 0.f;
#pragma unroll
        for (int q = 0; q < 16; q++) {
            float v0, v1; upk2(v[q], v0, v1);
            part2 += psi_s[(d0+2*q)*132 + p]*v0 + psi_s[(d0+2*q+1)*132 + p]*v1;
        }
        gred[half*128 + p] = part1 + part2;
    }
    __syncthreads();
    if (t < 128) {
        float gate = d_bp[0] + gred[t] + gred[128 + t];
        z_s[t] = 1.f / (1.f + __expf(-gate));   // da
    }
    __syncthreads();
    // ---- fused final multiply (float4 over positions) ----
    {
        int p4 = t & 31, c0 = t >> 5;
        float4 da = *(const float4*)&z_s[p4*4];
        const float* xp = x + ((size_t)b*256)*HWn + I0 + p4*4;
        float* op = out + ((size_t)b*256)*HWn + I0 + p4*4;
#pragma unroll 8
        for (int c = c0; c < 256; c += 8) {
            float4 v = *(const float4*)&xp[(size_t)c*HWn];
            v.x *= da.x; v.y *= da.y; v.z *= da.z; v.w *= da.w;
            *(float4*)&op[(size_t)c*HWn] = v;
        }
    }
}

// ---------------- launch ----------------
extern "C" void kernel_launch(void* const* d_in, const int* in_sizes, int n_in,
                              void* d_out, int out_size) {
    const float* g = (const float*)d_in[0];
    const float* x = (const float*)d_in[1];

    cudaFuncSetAttribute(k_psi2, cudaFuncAttributeMaxDynamicSharedMemorySize, 82176);
    cudaFuncSetAttribute(k_pam3, cudaFuncAttributeMaxDynamicSharedMemorySize, 102912);

    k_prep<<<128, 256>>>((const float*)d_in[2],  (const float*)d_in[3],  (const float*)d_in[4],
                        (const float*)d_in[5],  (const float*)d_in[6],  (const float*)d_in[7],
                        (const float*)d_in[8],  (const float*)d_in[9],  (const float*)d_in[10],
                        (const float*)d_in[11], (const float*)d_in[12], (const float*)d_in[13],
                        (const float*)d_in[14], (const float*)d_in[15], (const float*)d_in[16],
                        (const float*)d_in[17], (const float*)d_in[18], (const float*)d_in[19]);

    k_psi2<<<dim3(32, 8), 256, 82176>>>(g, x,
        (const float*)d_in[20], (const float*)d_in[21],
        (const float*)d_in[22], (const float*)d_in[23],
        (const float*)d_in[24], (const float*)d_in[25]);

    k_pam3<<<dim3(32, 8), 256, 102912>>>((const float*)d_in[26], (const float*)d_in[27],
                                         x, (float*)d_out);
}

// round 16
// speedup vs baseline: 1.0232x; 1.0232x over previous
#include <cuda_runtime.h>
#include <cuda_bf16.h>
#include <cuda_fp16.h>
#include <math.h>
#include <stdint.h>

typedef unsigned long long ull;

#define Bn 8
#define Cn 64
#define HWn 4096
#define LOG2E 1.4426950408889634f

// ---------------- scratch (device globals; no allocs allowed) ----------------
__device__ __align__(16) float d_psi[Bn*Cn*HWn];     // 8MB
__device__ __align__(16) float d_fb [Bn*8*HWn];      // pre-scaled by log2(e)
__device__ __align__(16) float d_fc [Bn*8*HWn];
__device__ __align__(16) char  d_fd2[Bn*64*8192];    // 4MB fp16, tile-major SWZ: [b][jt][SWZ(c*128+jp*4)]
__device__ __align__(16) float d_att[Bn*64*64];      // CAM gram (atomic-accumulated)
__device__ __align__(16) __nv_bfloat16 d_Wh[512*64]; // folded weight hi, [cin][out]
__device__ __align__(16) __nv_bfloat16 d_Wl[512*64]; // folded weight lo
__device__ __align__(16) float d_bias[64];
__device__ __align__(16) float d_wp[64];
__device__ __align__(16) float d_bp[1];

// ---------------- f32x2 helpers ----------------
__device__ __forceinline__ ull pk2(float lo, float hi) {
    ull r; asm("mov.b64 %0, {%1, %2};" : "=l"(r) : "f"(lo), "f"(hi)); return r;
}
__device__ __forceinline__ void upk2(ull v, float& lo, float& hi) {
    asm("mov.b64 {%0, %1}, %2;" : "=f"(lo), "=f"(hi) : "l"(v));
}
__device__ __forceinline__ ull ffma2(ull a, ull b, ull c) {
    ull d; asm("fma.rn.f32x2 %0, %1, %2, %3;" : "=l"(d) : "l"(a), "l"(b), "l"(c)); return d;
}
__device__ __forceinline__ float ex2f(float x) {
    float r; asm("ex2.approx.f32 %0, %1;" : "=f"(r) : "f"(x)); return r;
}

// ---------------- warp MMA helpers ----------------
__device__ __forceinline__ uint32_t smem_u32(const void* p) {
    uint32_t a;
    asm("{ .reg .u64 t; cvta.to.shared.u64 t, %1; cvt.u32.u64 %0, t; }" : "=r"(a) : "l"(p));
    return a;
}
#define SWZ(off) ((off) ^ (((off) >> 3) & 0x70))
__device__ __forceinline__ void ldsm_x4(uint32_t& r0, uint32_t& r1, uint32_t& r2, uint32_t& r3,
                                        uint32_t addr) {
    asm volatile("ldmatrix.sync.aligned.m8n8.x4.shared.b16 {%0,%1,%2,%3}, [%4];"
                 : "=r"(r0), "=r"(r1), "=r"(r2), "=r"(r3) : "r"(addr));
}
__device__ __forceinline__ void ldsm_x4t(uint32_t& r0, uint32_t& r1, uint32_t& r2, uint32_t& r3,
                                         uint32_t addr) {
    asm volatile("ldmatrix.sync.aligned.m8n8.x4.trans.shared.b16 {%0,%1,%2,%3}, [%4];"
                 : "=r"(r0), "=r"(r1), "=r"(r2), "=r"(r3) : "r"(addr));
}
__device__ __forceinline__ void mma_bf16(float* d, const uint32_t* a, const uint32_t* b) {
    asm volatile(
        "mma.sync.aligned.m16n8k16.row.col.f32.bf16.bf16.f32 "
        "{%0,%1,%2,%3}, {%4,%5,%6,%7}, {%8,%9}, {%0,%1,%2,%3};"
        : "+f"(d[0]), "+f"(d[1]), "+f"(d[2]), "+f"(d[3])
        : "r"(a[0]), "r"(a[1]), "r"(a[2]), "r"(a[3]), "r"(b[0]), "r"(b[1]));
}
__device__ __forceinline__ void mma_f16s(float* d, const uint32_t* a, uint32_t b0, uint32_t b1) {
    asm volatile(
        "mma.sync.aligned.m16n8k16.row.col.f32.f16.f16.f32 "
        "{%0,%1,%2,%3}, {%4,%5,%6,%7}, {%8,%9}, {%0,%1,%2,%3};"
        : "+f"(d[0]), "+f"(d[1]), "+f"(d[2]), "+f"(d[3])
        : "r"(a[0]), "r"(a[1]), "r"(a[2]), "r"(a[3]), "r"(b0), "r"(b1));
}
__device__ __forceinline__ uint32_t cvt_bf16x2(float a, float b) {
    uint32_t r;
    asm("cvt.rn.satfinite.bf16x2.f32 %0, %1, %2;" : "=r"(r) : "f"(b), "f"(a));
    return r;
}
__device__ __forceinline__ uint32_t cvt_f16x2(float a, float b) {
    // lower half = a, upper = b
    uint32_t r;
    asm("cvt.rn.f16x2.f32 %0, %1, %2;" : "=r"(r) : "f"(b), "f"(a));
    return r;
}
__device__ __forceinline__ uint32_t ex2h2(uint32_t a) {
    uint32_t r;
    asm("ex2.approx.f16x2 %0, %1;" : "=r"(r) : "r"(a));
    return r;
}
__device__ __forceinline__ uint32_t hadd2u(uint32_t a, uint32_t b) {
    uint32_t r;
    asm("add.rn.f16x2 %0, %1, %2;" : "=r"(r) : "r"(a), "r"(b));
    return r;
}

// ---------------- prep: double-coalesced transpose via smem ----------------
// grid 8 blocks: tile = (64 o) x (64 cin); reads AND writes coalesced.
__global__ void __launch_bounds__(256) k_prep(
                       const float* Wg_w, const float* Wg_b, const float* gg, const float* gb,
                       const float* gm, const float* gv,
                       const float* Wx_w, const float* Wx_b, const float* xg, const float* xb,
                       const float* xm, const float* xv,
                       const float* psi_w, const float* psi_b, const float* pg, const float* pbt,
                       const float* pm, const float* pv) {
    __shared__ float invs[64];
    __shared__ uint32_t sm[64*65];
    int t = threadIdx.x, tb = blockIdx.x;
    int set = tb >> 2;               // 0: g-weights, 1: x-weights
    int cin0 = (tb & 3) * 64;
    if (t < 64)
        invs[t] = set ? (xg[t] * rsqrtf(xv[t] + 1e-5f))
                      : (gg[t] * rsqrtf(gv[t] + 1e-5f));
    __syncthreads();
    const float* Ww = set ? Wx_w : Wg_w;
#pragma unroll
    for (int i = 0; i < 16; i++) {
        int idx = t + i*256;
        int o = idx >> 6, cin = idx & 63;
        float v = Ww[o*256 + cin0 + cin] * invs[o];      // coalesced read
        __nv_bfloat16 h = __float2bfloat16(v);
        __nv_bfloat16 l = __float2bfloat16(v - __bfloat162float(h));
        unsigned short hs = *(unsigned short*)&h;
        unsigned short ls = *(unsigned short*)&l;
        sm[cin*65 + o] = ((uint32_t)hs << 16) | ls;
    }
    // zero CAM gram accumulator (32768 floats over 8*256 threads)
#pragma unroll
    for (int i = 0; i < 16; i++)
        d_att[tb*4096 + t + i*256] = 0.f;
    __syncthreads();
#pragma unroll
    for (int i = 0; i < 16; i++) {
        int idx = t + i*256;
        int cin = idx >> 6, o = idx & 63;
        uint32_t pkd = sm[cin*65 + o];
        int row = set*256 + cin0 + cin;
        ((unsigned short*)d_Wh)[row*64 + o] = (unsigned short)(pkd >> 16);  // coalesced write
        ((unsigned short*)d_Wl)[row*64 + o] = (unsigned short)(pkd & 0xffffu);
    }
    if (tb == 0 && t < 64) {
        float invg = gg[t] * rsqrtf(gv[t] + 1e-5f);
        float invx = xg[t] * rsqrtf(xv[t] + 1e-5f);
        d_bias[t] = (Wg_b[t] - gm[t]) * invg + gb[t]
                  + (Wx_b[t] - xm[t]) * invx + xb[t];
        float invp = pg[0] * rsqrtf(pv[0] + 1e-5f);
        d_wp[t] = psi_w[t] * invp;
        if (t == 0) d_bp[0] = (psi_b[0] - pm[0]) * invp + pbt[0];
    }
}

// ---------------- psi via bf16-split HMMA + fused fb/fc/fd convs + CAM gram ----------------
__global__ void __launch_bounds__(256) k_psi2(const float* __restrict__ g, const float* __restrict__ x,
                                              const float* __restrict__ pb_w, const float* __restrict__ pb_b,
                                              const float* __restrict__ pc_w, const float* __restrict__ pc_b,
                                              const float* __restrict__ pd_w, const float* __restrict__ pd_b) {
    extern __shared__ __align__(1024) char ps[];
    uint32_t base = smem_u32(ps);
    uint32_t ahi = base, whi = base + 32768;
    float* f32s   = (float*)(ps + 49152);
    float* bias_s = (float*)(ps + 81920);
    float* psi_t  = (float*)ps;
    float* cw_s   = (float*)(ps + 33024);
    float* cbias  = (float*)(ps + 53504);
    char*  fds    = ps + 54272;

    int b = blockIdx.y, p0 = blockIdx.x*128, t = threadIdx.x;
    int w = t >> 5, lane = t & 31;
    if (t < 64) bias_s[t] = d_bias[t];

    float dfr[8][4];
#pragma unroll
    for (int nf = 0; nf < 8; nf++)
#pragma unroll
        for (int q = 0; q < 4; q++) dfr[nf][q] = 0.f;

    int r7 = lane & 7;
    int hsel = lane >> 4;
    uint32_t a_row = ahi + (uint32_t)(w*16 + (lane & 15))*128;
    uint32_t b_row = whi + (uint32_t)((((lane >> 3) & 1)*8 + r7))*128;

    for (int cb = 0; cb < 8; cb++) {
        __syncthreads();
        {
            const float* src = (cb < 4) ? g + ((size_t)b*256 + cb*64)*HWn
                                        : x + ((size_t)b*256 + (cb-4)*64)*HWn;
#pragma unroll
            for (int i = 0; i < 8; i++) {
                int idx = t + i*256;
                int c = idx >> 5, p4 = idx & 31;
                float4 v = *(const float4*)&src[(size_t)c*HWn + p0 + p4*4];
                *(float4*)&f32s[c*128 + p4*4] = v;
            }
        }
        {
#pragma unroll
            for (int q = 0; q < 2; q++) {
                int qi = t + q*256;
                int row = qi >> 3, qq = qi & 7;
                uint32_t so = SWZ((uint32_t)(row*128 + qq*16));
                *(uint4*)(ps + 32768 + so) =
                    *(const uint4*)((const char*)d_Wh + (size_t)(cb*64+row)*128 + qq*16);
                *(uint4*)(ps + 40960 + so) =
                    *(const uint4*)((const char*)d_Wl + (size_t)(cb*64+row)*128 + qq*16);
            }
        }
        __syncthreads();
        {
            int p = t & 127, half = t >> 7;
#pragma unroll
            for (int oct = 0; oct < 4; oct++) {
                int c0 = half*32 + oct*8;
                float v[8];
#pragma unroll
                for (int j = 0; j < 8; j++) v[j] = f32s[(c0+j)*128 + p];
                uint32_t uh[4], ul[4];
#pragma unroll
                for (int j = 0; j < 4; j++) {
                    uint32_t h = cvt_bf16x2(v[2*j], v[2*j+1]);
                    float h0 = __uint_as_float(h << 16);
                    float h1 = __uint_as_float(h & 0xffff0000u);
                    uh[j] = h;
                    ul[j] = cvt_bf16x2(v[2*j] - h0, v[2*j+1] - h1);
                }
                uint32_t so = SWZ((uint32_t)(p*128 + c0*2));
                *(uint4*)(ps + so)         = make_uint4(uh[0], uh[1], uh[2], uh[3]);
                *(uint4*)(ps + 16384 + so) = make_uint4(ul[0], ul[1], ul[2], ul[3]);
            }
        }
        __syncthreads();
        uint32_t afh[4][4], afl[4][4];
#pragma unroll
        for (int ks = 0; ks < 4; ks++) {
            uint32_t aq = (uint32_t)(((2*ks + hsel) ^ r7) * 16);
            ldsm_x4(afh[ks][0], afh[ks][1], afh[ks][2], afh[ks][3], a_row + aq);
            ldsm_x4(afl[ks][0], afl[ks][1], afl[ks][2], afl[ks][3], a_row + 16384 + aq);
        }
#pragma unroll
        for (int ks = 0; ks < 4; ks++) {
#pragma unroll
            for (int nn = 0; nn < 4; nn++) {
                uint32_t bq = (uint32_t)(((2*nn + hsel) ^ r7) * 16);
                uint32_t baddr = b_row + ks*2048 + bq;
                uint32_t bh[4], bl[4];
                ldsm_x4t(bh[0], bh[1], bh[2], bh[3], baddr);
                ldsm_x4t(bl[0], bl[1], bl[2], bl[3], baddr + 8192);
                mma_bf16(dfr[2*nn],   afh[ks], bh);
                mma_bf16(dfr[2*nn],   afh[ks], bl);
                mma_bf16(dfr[2*nn],   afl[ks], bh);
                mma_bf16(dfr[2*nn+1], afh[ks], bh + 2);
                mma_bf16(dfr[2*nn+1], afh[ks], bl + 2);
                mma_bf16(dfr[2*nn+1], afl[ks], bh + 2);
            }
        }
    }
    __syncthreads();
    // ---- epilogue 1: fragments -> psi_t [c][129], stage conv weights ----
    {
        int gr = lane >> 2, tc = lane & 3;
        int i1 = w*16 + gr, i2 = i1 + 8;
#pragma unroll
        for (int nf = 0; nf < 8; nf++) {
            int c0 = nf*8 + 2*tc;
            float b0 = bias_s[c0], b1 = bias_s[c0+1];
            psi_t[c0*129 + i1]     = fmaxf(dfr[nf][0] + b0, 0.f);
            psi_t[(c0+1)*129 + i1] = fmaxf(dfr[nf][1] + b1, 0.f);
            psi_t[c0*129 + i2]     = fmaxf(dfr[nf][2] + b0, 0.f);
            psi_t[(c0+1)*129 + i2] = fmaxf(dfr[nf][3] + b1, 0.f);
        }
    }
    for (int idx = t; idx < 5120; idx += 256) {
        int c = idx / 80, o = idx % 80;
        float wv;
        if (o < 8)       wv = pb_w[o*64 + c];
        else if (o < 16) wv = pc_w[(o-8)*64 + c];
        else             wv = pd_w[(o-16)*64 + c];
        cw_s[idx] = wv;
    }
    if (t < 80) cbias[t] = (t < 8) ? pb_b[t] : (t < 16 ? pc_b[t-8] : pd_b[t-16]);
    __syncthreads();
    // ---- epilogue 2: store psi, fb/fc convs; fd -> swizzled smem ----
    for (int idx = t; idx < 8192; idx += 256) {
        int c = idx >> 7, p = idx & 127;
        d_psi[((size_t)b*Cn + c)*HWn + p0 + p] = psi_t[c*129 + p];
    }
    {
        int pos = t & 127, half = t >> 7;
        int o0 = half*40;
        int tt = pos >> 6, jp = pos & 63;
        uint32_t fbase = (uint32_t)(tt*8192 + (jp & 1)*2);
        uint32_t fslot = (uint32_t)((jp >> 1)*4);
        ull acc[20];
#pragma unroll
        for (int q = 0; q < 20; q++) acc[q] = pk2(cbias[o0 + 2*q], cbias[o0 + 2*q + 1]);
        for (int c = 0; c < 64; c++) {
            float v = psi_t[c*129 + pos];
            ull v2 = pk2(v, v);
            const ull* wr = (const ull*)&cw_s[c*80 + o0];
#pragma unroll
            for (int q = 0; q < 20; q++) acc[q] = ffma2(v2, wr[q], acc[q]);
        }
#pragma unroll
        for (int q = 0; q < 20; q++) {
            float v0, v1; upk2(acc[q], v0, v1);
            int o = o0 + 2*q;
#pragma unroll
            for (int s = 0; s < 2; s++) {
                float v = s ? v1 : v0;
                int oo = o + s;
                if (oo < 8)       d_fb[((size_t)b*8 + oo)*HWn + p0 + pos] = v * LOG2E;
                else if (oo < 16) d_fc[((size_t)b*8 + (oo-8))*HWn + p0 + pos] = v;
                else {
                    int c = oo - 16;
                    *(__half*)(fds + fbase + SWZ((uint32_t)(c*128) + fslot)) = __float2half(v);
                }
            }
        }
    }
    __syncthreads();
    // ---- copy fd tiles to global (coalesced uint4) ----
    {
        char* fdst = d_fd2 + (size_t)b*524288 + (size_t)(blockIdx.x*2)*8192;
#pragma unroll
        for (int k = 0; k < 4; k++) {
            int idx = t + k*256;
            *(uint4*)(fdst + idx*16) = *(const uint4*)(fds + idx*16);
        }
    }
    // ---- CAM gram atomics ----
    {
        int cjg = t & 15, cig = t >> 4;
        float ga[4][4];
#pragma unroll
        for (int r = 0; r < 4; r++)
#pragma unroll
            for (int q = 0; q < 4; q++) ga[r][q] = 0.f;
        for (int p = 0; p < 128; p++) {
            float a0 = psi_t[(cig*4+0)*129 + p];
            float a1 = psi_t[(cig*4+1)*129 + p];
            float a2 = psi_t[(cig*4+2)*129 + p];
            float a3 = psi_t[(cig*4+3)*129 + p];
            float b0 = psi_t[(cjg*4+0)*129 + p];
            float b1 = psi_t[(cjg*4+1)*129 + p];
            float b2 = psi_t[(cjg*4+2)*129 + p];
            float b3 = psi_t[(cjg*4+3)*129 + p];
            ga[0][0]+=a0*b0; ga[0][1]+=a0*b1; ga[0][2]+=a0*b2; ga[0][3]+=a0*b3;
            ga[1][0]+=a1*b0; ga[1][1]+=a1*b1; ga[1][2]+=a1*b2; ga[1][3]+=a1*b3;
            ga[2][0]+=a2*b0; ga[2][1]+=a2*b1; ga[2][2]+=a2*b2; ga[2][3]+=a2*b3;
            ga[3][0]+=a3*b0; ga[3][1]+=a3*b1; ga[3][2]+=a3*b2; ga[3][3]+=a3*b3;
        }
#pragma unroll
        for (int r = 0; r < 4; r++)
#pragma unroll
            for (int q = 0; q < 4; q++)
                atomicAdd(&d_att[(b*64 + cig*4 + r)*64 + cjg*4 + q], ga[r][q]);
    }
}

// ---------------- PAM + CAM softmax + gate + final multiply ----------------
__global__ void __launch_bounds__(256, 2) k_pam3(const float* __restrict__ alpha_p,
                                                 const float* __restrict__ beta_p,
                                                 const float* __restrict__ x,
                                                 float* __restrict__ out) {
    extern __shared__ __align__(1024) char dsm[];
    float* psi_s = (float*)dsm;               // 64*132 f      0..33792
    float* pam_s = (float*)(dsm + 33792);     // 64*132 f      ..67584
    float* W2_s  = (float*)(dsm + 67584);     // 64*66 f       ..84480
    float* wp_s  = (float*)(dsm + 84480);     // 64 f          ..84736
    float* gred  = (float*)(dsm + 84736);     // 256 f         ..85760
    float* z_s   = (float*)(dsm + 85760);     // 128 f         ..86272
    float* att_s = (float*)(dsm + 86272);     // 64*65 f       ..102912

    uint32_t sbase = smem_u32(dsm);
    uint32_t fbb   = sbase + 16384;
    uint32_t fcb   = sbase + 22528;

    int b = blockIdx.y, I0 = blockIdx.x*128, t = threadIdx.x;
    int w = t >> 5, lane = t & 31;
    int gr = lane >> 2, tc = lane & 3;
    int i1 = w*16 + gr, i2 = i1 + 8;

    for (int idx = t; idx < 1024; idx += 256) {
        char* p;
        if (idx < 512) p = dsm + 16384 + (idx>>2)*48 + 16 + (idx&3)*4;
        else { int r = idx - 512; p = dsm + 22528 + (r>>2)*48 + 16 + (r&3)*4; }
        *(uint32_t*)p = 0u;
    }
    {
        int i = t & 127, half = t >> 7;
        float v0 = d_fb[((size_t)b*8 + half*4 + 0)*HWn + I0 + i];
        float v1 = d_fb[((size_t)b*8 + half*4 + 1)*HWn + I0 + i];
        float v2 = d_fb[((size_t)b*8 + half*4 + 2)*HWn + I0 + i];
        float v3 = d_fb[((size_t)b*8 + half*4 + 3)*HWn + I0 + i];
        *(uint32_t*)(dsm + 16384 + i*48 + half*8)     = cvt_f16x2(v0, v1);
        *(uint32_t*)(dsm + 16384 + i*48 + half*8 + 4) = cvt_f16x2(v2, v3);
    }
    __syncthreads();

    uint32_t af[4];
    {
        uint32_t aaddr = fbb + (uint32_t)(w*16 + (lane & 15))*48 + (lane >> 4)*16;
        ldsm_x4(af[0], af[1], af[2], af[3], aaddr);
    }

    float acc[8][4];
#pragma unroll
    for (int ng = 0; ng < 8; ng++)
#pragma unroll
        for (int q = 0; q < 4; q++) acc[ng][q] = 0.f;
    float z1 = 0.f, z2 = 0.f;
    float m1 = -1e30f, m2 = -1e30f;

    const char* fdg = d_fd2 + (size_t)b*524288;
    float fcr0, fcr1;
    uint4 fdr0, fdr1;
    {
        int j = t & 63, kp2 = t >> 6;
        fcr0 = d_fc[((size_t)b*8 + 2*kp2 + 0)*HWn + j];
        fcr1 = d_fc[((size_t)b*8 + 2*kp2 + 1)*HWn + j];
        fdr0 = *(const uint4*)(fdg + t*16);
        fdr1 = *(const uint4*)(fdg + 4096 + t*16);
    }

    uint32_t fdrow = (uint32_t)(lane & 15)*128 + (uint32_t)(lane >> 4)*16;

    for (int jt = 0; jt < 64; jt++) {
        uint32_t buf = (uint32_t)(jt & 1);
        {
            int j = t & 63, kp2 = t >> 6;
            *(uint32_t*)(dsm + 22528 + buf*3072 + j*48 + kp2*4) = cvt_f16x2(fcr0, fcr1);
        }
        *(uint4*)(dsm + buf*8192 + t*16)        = fdr0;
        *(uint4*)(dsm + buf*8192 + 4096 + t*16) = fdr1;
        __syncthreads();
        if (jt < 63) {
            int j0n = (jt+1)*64;
            int j = t & 63, kp2 = t >> 6;
            fcr0 = d_fc[((size_t)b*8 + 2*kp2 + 0)*HWn + j0n + j];
            fcr1 = d_fc[((size_t)b*8 + 2*kp2 + 1)*HWn + j0n + j];
            fdr0 = *(const uint4*)(fdg + (size_t)(jt+1)*8192 + t*16);
            fdr1 = *(const uint4*)(fdg + (size_t)(jt+1)*8192 + 4096 + t*16);
        }
        // energy mma (fp16 single product)
        float e[8][4];
#pragma unroll
        for (int ng = 0; ng < 8; ng++)
#pragma unroll
            for (int q = 0; q < 4; q++) e[ng][q] = 0.f;
#pragma unroll
        for (int jg = 0; jg < 4; jg++) {
            uint32_t baddr = fcb + buf*3072 + (uint32_t)(jg*16 + (lane & 15))*48 + (lane >> 4)*16;
            uint32_t bh[4];
            ldsm_x4(bh[0], bh[1], bh[2], bh[3], baddr);
            mma_f16s(e[2*jg],   af, bh[0], bh[2]);
            mma_f16s(e[2*jg+1], af, bh[1], bh[3]);
        }
        // online row max (quad shfl); rescale only when some row max moved
        float tm1 = -1e30f, tm2 = -1e30f;
#pragma unroll
        for (int ng = 0; ng < 8; ng++) {
            tm1 = fmaxf(tm1, fmaxf(e[ng][0], e[ng][1]));
            tm2 = fmaxf(tm2, fmaxf(e[ng][2], e[ng][3]));
        }
        tm1 = fmaxf(tm1, __shfl_xor_sync(0xffffffffu, tm1, 1));
        tm1 = fmaxf(tm1, __shfl_xor_sync(0xffffffffu, tm1, 2));
        tm2 = fmaxf(tm2, __shfl_xor_sync(0xffffffffu, tm2, 1));
        tm2 = fmaxf(tm2, __shfl_xor_sync(0xffffffffu, tm2, 2));
        float mn1 = fmaxf(m1, tm1), mn2 = fmaxf(m2, tm2);
        if (__any_sync(0xffffffffu, (mn1 > m1) || (mn2 > m2))) {
            float sc1 = ex2f(m1 - mn1), sc2 = ex2f(m2 - mn2);
            m1 = mn1; m2 = mn2;
            z1 *= sc1; z2 *= sc2;
#pragma unroll
            for (int ng = 0; ng < 8; ng++) {
                acc[ng][0] *= sc1; acc[ng][1] *= sc1;
                acc[ng][2] *= sc2; acc[ng][3] *= sc2;
            }
        }
        // exp via ex2.f16x2 -> p fragments
        uint32_t afr[4][4];
#pragma unroll
        for (int ng = 0; ng < 8; ng++) {
            uint32_t a01 = cvt_f16x2(e[ng][0] - m1, e[ng][1] - m1);
            uint32_t a23 = cvt_f16x2(e[ng][2] - m2, e[ng][3] - m2);
            uint32_t p01 = ex2h2(a01);
            uint32_t p23 = ex2h2(a23);
            int kp = ng >> 1;
            if ((ng & 1) == 0) { afr[kp][0] = p01; afr[kp][1] = p23; }
            else               { afr[kp][2] = p01; afr[kp][3] = p23; }
        }
        // z partial via HADD2 tree
        {
            uint32_t s1 = hadd2u(hadd2u(hadd2u(afr[0][0], afr[0][2]), hadd2u(afr[1][0], afr[1][2])),
                                 hadd2u(hadd2u(afr[2][0], afr[2][2]), hadd2u(afr[3][0], afr[3][2])));
            uint32_t s2 = hadd2u(hadd2u(hadd2u(afr[0][1], afr[0][3]), hadd2u(afr[1][1], afr[1][3])),
                                 hadd2u(hadd2u(afr[2][1], afr[2][3]), hadd2u(afr[3][1], afr[3][3])));
            float2 f1 = __half22float2(*(__half2*)&s1);
            float2 f2 = __half22float2(*(__half2*)&s2);
            z1 += f1.x + f1.y;
            z2 += f2.x + f2.y;
        }
        // accumulate mma (fp16)
#pragma unroll
        for (int ng2 = 0; ng2 < 4; ng2++) {
#pragma unroll
            for (int kp = 0; kp < 4; kp++) {
                uint32_t off = fdrow + (uint32_t)(ng2*2048 + kp*32);
                uint32_t f4[4];
                ldsm_x4(f4[0], f4[1], f4[2], f4[3], sbase + buf*8192 + SWZ(off));
                mma_f16s(acc[2*ng2],   afr[kp], f4[0], f4[2]);
                mma_f16s(acc[2*ng2+1], afr[kp], f4[1], f4[3]);
            }
        }
    }
    // ---- z reduction across the quad ----
    z1 += __shfl_xor_sync(0xffffffffu, z1, 1);
    z1 += __shfl_xor_sync(0xffffffffu, z1, 2);
    z2 += __shfl_xor_sync(0xffffffffu, z2, 1);
    z2 += __shfl_xor_sync(0xffffffffu, z2, 2);
    if (tc == 0) {
        z_s[i1] = alpha_p[0] / z1;
        z_s[i2] = alpha_p[0] / z2;
    }
    __syncthreads();
    // ---- load psi tile / att / wp ----
    for (int idx = t; idx < 8192; idx += 256) {
        int c = idx >> 7, p = idx & 127;
        psi_s[c*132 + p] = d_psi[((size_t)b*Cn + c)*HWn + I0 + p];
    }
    for (int idx = t; idx < 4096; idx += 256)
        att_s[(idx >> 6)*65 + (idx & 63)] = d_att[b*4096 + idx];
    if (t < 64) wp_s[t] = d_wp[t];
    __syncthreads();
    // ---- CAM softmax -> W2_s[c][66] (4 threads per row) ----
    {
        int r = t >> 2, q4 = t & 3;
        float v[16];
#pragma unroll
        for (int k = 0; k < 16; k++) v[k] = att_s[r*65 + q4*16 + k];
        float mx = -1e30f, mn = 1e30f;
#pragma unroll
        for (int k = 0; k < 16; k++) { mx = fmaxf(mx, v[k]); mn = fminf(mn, v[k]); }
        mx = fmaxf(mx, __shfl_xor_sync(0xffffffffu, mx, 1));
        mx = fmaxf(mx, __shfl_xor_sync(0xffffffffu, mx, 2));
        mn = fminf(mn, __shfl_xor_sync(0xffffffffu, mn, 1));
        mn = fminf(mn, __shfl_xor_sync(0xffffffffu, mn, 2));
        float m2r = mx - mn;
        float ssum = 0.f;
#pragma unroll
        for (int k = 0; k < 16; k++) { float ev = __expf((mx - v[k]) - m2r); v[k] = ev; ssum += ev; }
        ssum += __shfl_xor_sync(0xffffffffu, ssum, 1);
        ssum += __shfl_xor_sync(0xffffffffu, ssum, 2);
        float scale = beta_p[0] * wp_s[r] / ssum;
#pragma unroll
        for (int k = 0; k < 16; k++) W2_s[r*66 + q4*16 + k] = v[k] * scale;
    }
    // ---- fragments -> pam_s[c][i] ----
    {
        float zz1 = z_s[i1], zz2 = z_s[i2];
#pragma unroll
        for (int ng = 0; ng < 8; ng++) {
            int c = ng*8 + 2*tc;
            pam_s[c*132 + i1]     = acc[ng][0]*zz1 + psi_s[c*132 + i1];
            pam_s[(c+1)*132 + i1] = acc[ng][1]*zz1 + psi_s[(c+1)*132 + i1];
            pam_s[c*132 + i2]     = acc[ng][2]*zz2 + psi_s[c*132 + i2];
            pam_s[(c+1)*132 + i2] = acc[ng][3]*zz2 + psi_s[(c+1)*132 + i2];
        }
    }
    __syncthreads();
    // ---- fused CAM + gate ----
    {
        int p = t & 127, half = t >> 7;
        int c0 = half*32, d0 = half*32;
        float part1 = 0.f;
#pragma unroll 8
        for (int c = 0; c < 32; c++) {
            int cc = c0 + c;
            part1 += wp_s[cc] * psi_s[cc*132 + p] * pam_s[cc*132 + p];
        }
        ull v[16];
#pragma unroll
        for (int q = 0; q < 16; q++) v[q] = 0ull;
        for (int c = 0; c < 64; c++) {
            float pm = pam_s[c*132 + p];
            ull pm2 = pk2(pm, pm);
            const ull* wr = (const ull*)&W2_s[c*66 + d0];
#pragma unroll
            for (int q = 0; q < 16; q++) v[q] = ffma2(pm2, wr[q], v[q]);
        }
        float part2 = 0.f;
#pragma unroll
        for (int q = 0; q < 16; q++) {
            float v0, v1; upk2(v[q], v0, v1);
            part2 += psi_s[(d0+2*q)*132 + p]*v0 + psi_s[(d0+2*q+1)*132 + p]*v1;
        }
        gred[half*128 + p] = part1 + part2;
    }
    __syncthreads();
    if (t < 128) {
        float gate = d_bp[0] + gred[t] + gred[128 + t];
        z_s[t] = 1.f / (1.f + __expf(-gate));   // da
    }
    __syncthreads();
    // ---- fused final multiply (float4 over positions) ----
    {
        int p4 = t & 31, c0 = t >> 5;
        float4 da = *(const float4*)&z_s[p4*4];
        const float* xp = x + ((size_t)b*256)*HWn + I0 + p4*4;
        float* op = out + ((size_t)b*256)*HWn + I0 + p4*4;
#pragma unroll 8
        for (int c = c0; c < 256; c += 8) {
            float4 v = *(const float4*)&xp[(size_t)c*HWn];
            v.x *= da.x; v.y *= da.y; v.z *= da.z; v.w *= da.w;
            *(float4*)&op[(size_t)c*HWn] = v;
        }
    }
}

// ---------------- launch ----------------
extern "C" void kernel_launch(void* const* d_in, const int* in_sizes, int n_in,
                              void* d_out, int out_size) {
    const float* g = (const float*)d_in[0];
    const float* x = (const float*)d_in[1];

    cudaFuncSetAttribute(k_psi2, cudaFuncAttributeMaxDynamicSharedMemorySize, 82176);
    cudaFuncSetAttribute(k_pam3, cudaFuncAttributeMaxDynamicSharedMemorySize, 102912);

    k_prep<<<8, 256>>>((const float*)d_in[2],  (const float*)d_in[3],  (const float*)d_in[4],
                        (const float*)d_in[5],  (const float*)d_in[6],  (const float*)d_in[7],
                        (const float*)d_in[8],  (const float*)d_in[9],  (const float*)d_in[10],
                        (const float*)d_in[11], (const float*)d_in[12], (const float*)d_in[13],
                        (const float*)d_in[14], (const float*)d_in[15], (const float*)d_in[16],
                        (const float*)d_in[17], (const float*)d_in[18], (const float*)d_in[19]);

    k_psi2<<<dim3(32, 8), 256, 82176>>>(g, x,
        (const float*)d_in[20], (const float*)d_in[21],
        (const float*)d_in[22], (const float*)d_in[23],
        (const float*)d_in[24], (const float*)d_in[25]);

    k_pam3<<<dim3(32, 8), 256, 102912>>>((const float*)d_in[26], (const float*)d_in[27],
                                         x, (float*)d_out);
}

// round 17
// speedup vs baseline: 1.0249x; 1.0017x over previous
#include <cuda_runtime.h>
#include <cuda_bf16.h>
#include <cuda_fp16.h>
#include <math.h>
#include <stdint.h>

typedef unsigned long long ull;

#define Bn 8
#define Cn 64
#define HWn 4096
#define LOG2E 1.4426950408889634f

// ---------------- scratch (device globals; no allocs allowed) ----------------
__device__ __align__(16) float d_psi[Bn*Cn*HWn];     // 8MB
__device__ __align__(16) float d_fb [Bn*8*HWn];      // pre-scaled by log2(e)
__device__ __align__(16) float d_fc [Bn*8*HWn];
__device__ __align__(16) char  d_fd2[Bn*64*8192];    // 4MB fp16, tile-major SWZ: [b][jt][SWZ(c*128+jp*4)]
__device__ __align__(16) float d_att[Bn*64*64];      // CAM gram (atomic-accumulated)
__device__ __align__(16) __nv_bfloat16 d_Wh[512*64]; // folded weight hi, [cin][out]
__device__ __align__(16) __nv_bfloat16 d_Wl[512*64]; // folded weight lo
__device__ __align__(16) float d_bias[64];
__device__ __align__(16) float d_wp[64];
__device__ __align__(16) float d_bp[1];

// ---------------- f32x2 helpers ----------------
__device__ __forceinline__ ull pk2(float lo, float hi) {
    ull r; asm("mov.b64 %0, {%1, %2};" : "=l"(r) : "f"(lo), "f"(hi)); return r;
}
__device__ __forceinline__ void upk2(ull v, float& lo, float& hi) {
    asm("mov.b64 {%0, %1}, %2;" : "=f"(lo), "=f"(hi) : "l"(v));
}
__device__ __forceinline__ ull ffma2(ull a, ull b, ull c) {
    ull d; asm("fma.rn.f32x2 %0, %1, %2, %3;" : "=l"(d) : "l"(a), "l"(b), "l"(c)); return d;
}
__device__ __forceinline__ float ex2f(float x) {
    float r; asm("ex2.approx.f32 %0, %1;" : "=f"(r) : "f"(x)); return r;
}

// ---------------- warp MMA helpers ----------------
__device__ __forceinline__ uint32_t smem_u32(const void* p) {
    uint32_t a;
    asm("{ .reg .u64 t; cvta.to.shared.u64 t, %1; cvt.u32.u64 %0, t; }" : "=r"(a) : "l"(p));
    return a;
}
#define SWZ(off) ((off) ^ (((off) >> 3) & 0x70))
__device__ __forceinline__ void ldsm_x4(uint32_t& r0, uint32_t& r1, uint32_t& r2, uint32_t& r3,
                                        uint32_t addr) {
    asm volatile("ldmatrix.sync.aligned.m8n8.x4.shared.b16 {%0,%1,%2,%3}, [%4];"
                 : "=r"(r0), "=r"(r1), "=r"(r2), "=r"(r3) : "r"(addr));
}
__device__ __forceinline__ void ldsm_x4t(uint32_t& r0, uint32_t& r1, uint32_t& r2, uint32_t& r3,
                                         uint32_t addr) {
    asm volatile("ldmatrix.sync.aligned.m8n8.x4.trans.shared.b16 {%0,%1,%2,%3}, [%4];"
                 : "=r"(r0), "=r"(r1), "=r"(r2), "=r"(r3) : "r"(addr));
}
__device__ __forceinline__ void mma_bf16(float* d, const uint32_t* a, const uint32_t* b) {
    asm volatile(
        "mma.sync.aligned.m16n8k16.row.col.f32.bf16.bf16.f32 "
        "{%0,%1,%2,%3}, {%4,%5,%6,%7}, {%8,%9}, {%0,%1,%2,%3};"
        : "+f"(d[0]), "+f"(d[1]), "+f"(d[2]), "+f"(d[3])
        : "r"(a[0]), "r"(a[1]), "r"(a[2]), "r"(a[3]), "r"(b[0]), "r"(b[1]));
}
__device__ __forceinline__ void mma_f16s(float* d, const uint32_t* a, uint32_t b0, uint32_t b1) {
    asm volatile(
        "mma.sync.aligned.m16n8k16.row.col.f32.f16.f16.f32 "
        "{%0,%1,%2,%3}, {%4,%5,%6,%7}, {%8,%9}, {%0,%1,%2,%3};"
        : "+f"(d[0]), "+f"(d[1]), "+f"(d[2]), "+f"(d[3])
        : "r"(a[0]), "r"(a[1]), "r"(a[2]), "r"(a[3]), "r"(b0), "r"(b1));
}
__device__ __forceinline__ uint32_t cvt_bf16x2(float a, float b) {
    uint32_t r;
    asm("cvt.rn.satfinite.bf16x2.f32 %0, %1, %2;" : "=r"(r) : "f"(b), "f"(a));
    return r;
}
__device__ __forceinline__ uint32_t cvt_f16x2(float a, float b) {
    // lower half = a, upper = b
    uint32_t r;
    asm("cvt.rn.f16x2.f32 %0, %1, %2;" : "=r"(r) : "f"(b), "f"(a));
    return r;
}
__device__ __forceinline__ uint32_t ex2h2(uint32_t a) {
    uint32_t r;
    asm("ex2.approx.f16x2 %0, %1;" : "=r"(r) : "r"(a));
    return r;
}
__device__ __forceinline__ uint32_t hadd2u(uint32_t a, uint32_t b) {
    uint32_t r;
    asm("add.rn.f16x2 %0, %1, %2;" : "=r"(r) : "r"(a), "r"(b));
    return r;
}

// ---------------- prep (R13 form: 128 blocks, coalesced stores, smem BN cache) ----------------
__global__ void __launch_bounds__(256) k_prep(
                       const float* Wg_w, const float* Wg_b, const float* gg, const float* gb,
                       const float* gm, const float* gv,
                       const float* Wx_w, const float* Wx_b, const float* xg, const float* xb,
                       const float* xm, const float* xv,
                       const float* psi_w, const float* psi_b, const float* pg, const float* pbt,
                       const float* pm, const float* pv) {
    __shared__ float invs[128];
    int t = threadIdx.x;
    if (t < 64)       invs[t] = gg[t] * rsqrtf(gv[t] + 1e-5f);
    else if (t < 128) invs[t] = xg[t-64] * rsqrtf(xv[t-64] + 1e-5f);
    __syncthreads();
    int r = blockIdx.x*4 + (t >> 6);
    int o = t & 63;
    int set = r >> 8;
    int cin = r & 255;
    const float* Ww = set ? Wx_w : Wg_w;
    float v = Ww[o*256 + cin] * invs[set*64 + o];
    __nv_bfloat16 h = __float2bfloat16(v);
    d_Wh[r*64 + o] = h;
    d_Wl[r*64 + o] = __float2bfloat16(v - __bfloat162float(h));
    d_att[blockIdx.x*256 + t] = 0.f;
    if (r == 0) {
        d_bias[o] = (Wg_b[o] - gm[o]) * invs[o] + gb[o]
                  + (Wx_b[o] - xm[o]) * invs[64 + o] + xb[o];
        float invp = pg[0] * rsqrtf(pv[0] + 1e-5f);
        d_wp[o] = psi_w[o] * invp;
        if (o == 0) d_bp[0] = (psi_b[0] - pm[0]) * invp + pbt[0];
    }
}

// ---------------- psi via bf16-split HMMA + fused fb/fc/fd convs + CAM gram (R13) ----------------
__global__ void __launch_bounds__(256) k_psi2(const float* __restrict__ g, const float* __restrict__ x,
                                              const float* __restrict__ pb_w, const float* __restrict__ pb_b,
                                              const float* __restrict__ pc_w, const float* __restrict__ pc_b,
                                              const float* __restrict__ pd_w, const float* __restrict__ pd_b) {
    extern __shared__ __align__(1024) char ps[];
    uint32_t base = smem_u32(ps);
    uint32_t ahi = base, whi = base + 32768;
    float* f32s   = (float*)(ps + 49152);
    float* bias_s = (float*)(ps + 81920);
    float* psi_t  = (float*)ps;
    float* cw_s   = (float*)(ps + 33024);
    float* cbias  = (float*)(ps + 53504);
    char*  fds    = ps + 54272;

    int b = blockIdx.y, p0 = blockIdx.x*128, t = threadIdx.x;
    int w = t >> 5, lane = t & 31;
    if (t < 64) bias_s[t] = d_bias[t];

    float dfr[8][4];
#pragma unroll
    for (int nf = 0; nf < 8; nf++)
#pragma unroll
        for (int q = 0; q < 4; q++) dfr[nf][q] = 0.f;

    int r7 = lane & 7;
    int hsel = lane >> 4;
    uint32_t a_row = ahi + (uint32_t)(w*16 + (lane & 15))*128;
    uint32_t b_row = whi + (uint32_t)((((lane >> 3) & 1)*8 + r7))*128;

    for (int cb = 0; cb < 8; cb++) {
        __syncthreads();
        {
            const float* src = (cb < 4) ? g + ((size_t)b*256 + cb*64)*HWn
                                        : x + ((size_t)b*256 + (cb-4)*64)*HWn;
#pragma unroll
            for (int i = 0; i < 8; i++) {
                int idx = t + i*256;
                int c = idx >> 5, p4 = idx & 31;
                float4 v = *(const float4*)&src[(size_t)c*HWn + p0 + p4*4];
                *(float4*)&f32s[c*128 + p4*4] = v;
            }
        }
        {
#pragma unroll
            for (int q = 0; q < 2; q++) {
                int qi = t + q*256;
                int row = qi >> 3, qq = qi & 7;
                uint32_t so = SWZ((uint32_t)(row*128 + qq*16));
                *(uint4*)(ps + 32768 + so) =
                    *(const uint4*)((const char*)d_Wh + (size_t)(cb*64+row)*128 + qq*16);
                *(uint4*)(ps + 40960 + so) =
                    *(const uint4*)((const char*)d_Wl + (size_t)(cb*64+row)*128 + qq*16);
            }
        }
        __syncthreads();
        {
            int p = t & 127, half = t >> 7;
#pragma unroll
            for (int oct = 0; oct < 4; oct++) {
                int c0 = half*32 + oct*8;
                float v[8];
#pragma unroll
                for (int j = 0; j < 8; j++) v[j] = f32s[(c0+j)*128 + p];
                uint32_t uh[4], ul[4];
#pragma unroll
                for (int j = 0; j < 4; j++) {
                    uint32_t h = cvt_bf16x2(v[2*j], v[2*j+1]);
                    float h0 = __uint_as_float(h << 16);
                    float h1 = __uint_as_float(h & 0xffff0000u);
                    uh[j] = h;
                    ul[j] = cvt_bf16x2(v[2*j] - h0, v[2*j+1] - h1);
                }
                uint32_t so = SWZ((uint32_t)(p*128 + c0*2));
                *(uint4*)(ps + so)         = make_uint4(uh[0], uh[1], uh[2], uh[3]);
                *(uint4*)(ps + 16384 + so) = make_uint4(ul[0], ul[1], ul[2], ul[3]);
            }
        }
        __syncthreads();
        uint32_t afh[4][4], afl[4][4];
#pragma unroll
        for (int ks = 0; ks < 4; ks++) {
            uint32_t aq = (uint32_t)(((2*ks + hsel) ^ r7) * 16);
            ldsm_x4(afh[ks][0], afh[ks][1], afh[ks][2], afh[ks][3], a_row + aq);
            ldsm_x4(afl[ks][0], afl[ks][1], afl[ks][2], afl[ks][3], a_row + 16384 + aq);
        }
#pragma unroll
        for (int ks = 0; ks < 4; ks++) {
#pragma unroll
            for (int nn = 0; nn < 4; nn++) {
                uint32_t bq = (uint32_t)(((2*nn + hsel) ^ r7) * 16);
                uint32_t baddr = b_row + ks*2048 + bq;
                uint32_t bh[4], bl[4];
                ldsm_x4t(bh[0], bh[1], bh[2], bh[3], baddr);
                ldsm_x4t(bl[0], bl[1], bl[2], bl[3], baddr + 8192);
                mma_bf16(dfr[2*nn],   afh[ks], bh);
                mma_bf16(dfr[2*nn],   afh[ks], bl);
                mma_bf16(dfr[2*nn],   afl[ks], bh);
                mma_bf16(dfr[2*nn+1], afh[ks], bh + 2);
                mma_bf16(dfr[2*nn+1], afh[ks], bl + 2);
                mma_bf16(dfr[2*nn+1], afl[ks], bh + 2);
            }
        }
    }
    __syncthreads();
    // ---- epilogue 1: fragments -> psi_t [c][129], stage conv weights ----
    {
        int gr = lane >> 2, tc = lane & 3;
        int i1 = w*16 + gr, i2 = i1 + 8;
#pragma unroll
        for (int nf = 0; nf < 8; nf++) {
            int c0 = nf*8 + 2*tc;
            float b0 = bias_s[c0], b1 = bias_s[c0+1];
            psi_t[c0*129 + i1]     = fmaxf(dfr[nf][0] + b0, 0.f);
            psi_t[(c0+1)*129 + i1] = fmaxf(dfr[nf][1] + b1, 0.f);
            psi_t[c0*129 + i2]     = fmaxf(dfr[nf][2] + b0, 0.f);
            psi_t[(c0+1)*129 + i2] = fmaxf(dfr[nf][3] + b1, 0.f);
        }
    }
    for (int idx = t; idx < 5120; idx += 256) {
        int c = idx / 80, o = idx % 80;
        float wv;
        if (o < 8)       wv = pb_w[o*64 + c];
        else if (o < 16) wv = pc_w[(o-8)*64 + c];
        else             wv = pd_w[(o-16)*64 + c];
        cw_s[idx] = wv;
    }
    if (t < 80) cbias[t] = (t < 8) ? pb_b[t] : (t < 16 ? pc_b[t-8] : pd_b[t-16]);
    __syncthreads();
    // ---- epilogue 2: store psi, fb/fc convs; fd -> swizzled smem ----
    for (int idx = t; idx < 8192; idx += 256) {
        int c = idx >> 7, p = idx & 127;
        d_psi[((size_t)b*Cn + c)*HWn + p0 + p] = psi_t[c*129 + p];
    }
    {
        int pos = t & 127, half = t >> 7;
        int o0 = half*40;
        int tt = pos >> 6, jp = pos & 63;
        uint32_t fbase = (uint32_t)(tt*8192 + (jp & 1)*2);
        uint32_t fslot = (uint32_t)((jp >> 1)*4);
        ull acc[20];
#pragma unroll
        for (int q = 0; q < 20; q++) acc[q] = pk2(cbias[o0 + 2*q], cbias[o0 + 2*q + 1]);
        for (int c = 0; c < 64; c++) {
            float v = psi_t[c*129 + pos];
            ull v2 = pk2(v, v);
            const ull* wr = (const ull*)&cw_s[c*80 + o0];
#pragma unroll
            for (int q = 0; q < 20; q++) acc[q] = ffma2(v2, wr[q], acc[q]);
        }
#pragma unroll
        for (int q = 0; q < 20; q++) {
            float v0, v1; upk2(acc[q], v0, v1);
            int o = o0 + 2*q;
#pragma unroll
            for (int s = 0; s < 2; s++) {
                float v = s ? v1 : v0;
                int oo = o + s;
                if (oo < 8)       d_fb[((size_t)b*8 + oo)*HWn + p0 + pos] = v * LOG2E;
                else if (oo < 16) d_fc[((size_t)b*8 + (oo-8))*HWn + p0 + pos] = v;
                else {
                    int c = oo - 16;
                    *(__half*)(fds + fbase + SWZ((uint32_t)(c*128) + fslot)) = __float2half(v);
                }
            }
        }
    }
    __syncthreads();
    // ---- copy fd tiles to global (coalesced uint4) ----
    {
        char* fdst = d_fd2 + (size_t)b*524288 + (size_t)(blockIdx.x*2)*8192;
#pragma unroll
        for (int k = 0; k < 4; k++) {
            int idx = t + k*256;
            *(uint4*)(fdst + idx*16) = *(const uint4*)(fds + idx*16);
        }
    }
    // ---- CAM gram atomics ----
    {
        int cjg = t & 15, cig = t >> 4;
        float ga[4][4];
#pragma unroll
        for (int r = 0; r < 4; r++)
#pragma unroll
            for (int q = 0; q < 4; q++) ga[r][q] = 0.f;
        for (int p = 0; p < 128; p++) {
            float a0 = psi_t[(cig*4+0)*129 + p];
            float a1 = psi_t[(cig*4+1)*129 + p];
            float a2 = psi_t[(cig*4+2)*129 + p];
            float a3 = psi_t[(cig*4+3)*129 + p];
            float b0 = psi_t[(cjg*4+0)*129 + p];
            float b1 = psi_t[(cjg*4+1)*129 + p];
            float b2 = psi_t[(cjg*4+2)*129 + p];
            float b3 = psi_t[(cjg*4+3)*129 + p];
            ga[0][0]+=a0*b0; ga[0][1]+=a0*b1; ga[0][2]+=a0*b2; ga[0][3]+=a0*b3;
            ga[1][0]+=a1*b0; ga[1][1]+=a1*b1; ga[1][2]+=a1*b2; ga[1][3]+=a1*b3;
            ga[2][0]+=a2*b0; ga[2][1]+=a2*b1; ga[2][2]+=a2*b2; ga[2][3]+=a2*b3;
            ga[3][0]+=a3*b0; ga[3][1]+=a3*b1; ga[3][2]+=a3*b2; ga[3][3]+=a3*b3;
        }
#pragma unroll
        for (int r = 0; r < 4; r++)
#pragma unroll
            for (int q = 0; q < 4; q++)
                atomicAdd(&d_att[(b*64 + cig*4 + r)*64 + cjg*4 + q], ga[r][q]);
    }
}

// ---------------- PAM + CAM softmax + gate + final multiply ----------------
// Staging at 128-j granularity (ONE sync per 2 tiles); compute in 64-j sub-steps
// with the exact R13 sequence (bit-identical numerics).
// Mainloop smem: fd 2x16384 @0 | fb 128x48 @32768 | fc 2x6144 @38912 (..51200)
__global__ void __launch_bounds__(256, 2) k_pam3(const float* __restrict__ alpha_p,
                                                 const float* __restrict__ beta_p,
                                                 const float* __restrict__ x,
                                                 float* __restrict__ out) {
    extern __shared__ __align__(1024) char dsm[];
    float* psi_s = (float*)dsm;               // 64*132 f      0..33792
    float* pam_s = (float*)(dsm + 33792);     // 64*132 f      ..67584
    float* W2_s  = (float*)(dsm + 67584);     // 64*66 f       ..84480
    float* wp_s  = (float*)(dsm + 84480);     // 64 f          ..84736
    float* gred  = (float*)(dsm + 84736);     // 256 f         ..85760
    float* z_s   = (float*)(dsm + 85760);     // 128 f         ..86272
    float* att_s = (float*)(dsm + 86272);     // 64*65 f       ..102912

    uint32_t sbase = smem_u32(dsm);
    uint32_t fbb   = sbase + 32768;
    uint32_t fcb   = sbase + 38912;

    int b = blockIdx.y, I0 = blockIdx.x*128, t = threadIdx.x;
    int w = t >> 5, lane = t & 31;
    int gr = lane >> 2, tc = lane & 3;
    int i1 = w*16 + gr, i2 = i1 + 8;

    // zero pads: fb 128 rows x 16B (512 u32) + fc 2 bufs x 128 rows x 16B (1024 u32)
    for (int idx = t; idx < 1536; idx += 256) {
        char* p;
        if (idx < 512) p = dsm + 32768 + (idx>>2)*48 + 16 + (idx&3)*4;
        else { int r = idx - 512; p = dsm + 38912 + (r>>2)*48 + 16 + (r&3)*4; }
        *(uint32_t*)p = 0u;
    }
    // stage fb fp16 [i][k] (48B rows)
    {
        int i = t & 127, half = t >> 7;
        float v0 = d_fb[((size_t)b*8 + half*4 + 0)*HWn + I0 + i];
        float v1 = d_fb[((size_t)b*8 + half*4 + 1)*HWn + I0 + i];
        float v2 = d_fb[((size_t)b*8 + half*4 + 2)*HWn + I0 + i];
        float v3 = d_fb[((size_t)b*8 + half*4 + 3)*HWn + I0 + i];
        *(uint32_t*)(dsm + 32768 + i*48 + half*8)     = cvt_f16x2(v0, v1);
        *(uint32_t*)(dsm + 32768 + i*48 + half*8 + 4) = cvt_f16x2(v2, v3);
    }
    __syncthreads();

    uint32_t af[4];
    {
        uint32_t aaddr = fbb + (uint32_t)(w*16 + (lane & 15))*48 + (lane >> 4)*16;
        ldsm_x4(af[0], af[1], af[2], af[3], aaddr);
    }

    float acc[8][4];
#pragma unroll
    for (int ng = 0; ng < 8; ng++)
#pragma unroll
        for (int q = 0; q < 4; q++) acc[ng][q] = 0.f;
    float z1 = 0.f, z2 = 0.f;
    float m1 = -1e30f, m2 = -1e30f;

    const char* fdg = d_fd2 + (size_t)b*524288;
    // prefetch for 128-j block 0: fc 4 ch values at row jj, fd 4 uint4
    int jj = t & 127, kq = t >> 7;       // kq: 0 or 1 -> channels 4kq..4kq+3
    float fcr[4];
    uint4 fdr[4];
    {
#pragma unroll
        for (int s = 0; s < 4; s++)
            fcr[s] = d_fc[((size_t)b*8 + 4*kq + s)*HWn + jj];
#pragma unroll
        for (int q = 0; q < 4; q++)
            fdr[q] = *(const uint4*)(fdg + (t + q*256)*16);
    }

    uint32_t fdrow = (uint32_t)(lane & 15)*128 + (uint32_t)(lane >> 4)*16;

    for (int jt2 = 0; jt2 < 32; jt2++) {
        uint32_t buf = (uint32_t)(jt2 & 1);
        // store staged regs into buf (128-j block)
        *(uint32_t*)(dsm + 38912 + buf*6144 + jj*48 + (2*kq)*4)     = cvt_f16x2(fcr[0], fcr[1]);
        *(uint32_t*)(dsm + 38912 + buf*6144 + jj*48 + (2*kq + 1)*4) = cvt_f16x2(fcr[2], fcr[3]);
#pragma unroll
        for (int q = 0; q < 4; q++)
            *(uint4*)(dsm + buf*16384 + (t + q*256)*16) = fdr[q];
        __syncthreads();
        // prefetch next 128-j block
        if (jt2 < 31) {
            int j0n = (jt2+1)*128;
#pragma unroll
            for (int s = 0; s < 4; s++)
                fcr[s] = d_fc[((size_t)b*8 + 4*kq + s)*HWn + j0n + jj];
#pragma unroll
            for (int q = 0; q < 4; q++)
                fdr[q] = *(const uint4*)(fdg + (size_t)(jt2+1)*16384 + (t + q*256)*16);
        }
        // two 64-j sub-steps, identical to R13 per-tile body
#pragma unroll
        for (int hs = 0; hs < 2; hs++) {
            // energy mma (fp16 single product)
            float e[8][4];
#pragma unroll
            for (int ng = 0; ng < 8; ng++)
#pragma unroll
                for (int q = 0; q < 4; q++) e[ng][q] = 0.f;
#pragma unroll
            for (int jg = 0; jg < 4; jg++) {
                uint32_t baddr = fcb + buf*6144 + (uint32_t)(hs*64 + jg*16 + (lane & 15))*48 + (lane >> 4)*16;
                uint32_t bh[4];
                ldsm_x4(bh[0], bh[1], bh[2], bh[3], baddr);
                mma_f16s(e[2*jg],   af, bh[0], bh[2]);
                mma_f16s(e[2*jg+1], af, bh[1], bh[3]);
            }
            // online row max (quad shfl); rescale only when moved (vote)
            float tm1 = -1e30f, tm2 = -1e30f;
#pragma unroll
            for (int ng = 0; ng < 8; ng++) {
                tm1 = fmaxf(tm1, fmaxf(e[ng][0], e[ng][1]));
                tm2 = fmaxf(tm2, fmaxf(e[ng][2], e[ng][3]));
            }
            tm1 = fmaxf(tm1, __shfl_xor_sync(0xffffffffu, tm1, 1));
            tm1 = fmaxf(tm1, __shfl_xor_sync(0xffffffffu, tm1, 2));
            tm2 = fmaxf(tm2, __shfl_xor_sync(0xffffffffu, tm2, 1));
            tm2 = fmaxf(tm2, __shfl_xor_sync(0xffffffffu, tm2, 2));
            float mn1 = fmaxf(m1, tm1), mn2 = fmaxf(m2, tm2);
            if (__any_sync(0xffffffffu, (mn1 > m1) || (mn2 > m2))) {
                float sc1 = ex2f(m1 - mn1), sc2 = ex2f(m2 - mn2);
                m1 = mn1; m2 = mn2;
                z1 *= sc1; z2 *= sc2;
#pragma unroll
                for (int ng = 0; ng < 8; ng++) {
                    acc[ng][0] *= sc1; acc[ng][1] *= sc1;
                    acc[ng][2] *= sc2; acc[ng][3] *= sc2;
                }
            }
            // exp via ex2.f16x2 -> p fragments
            uint32_t afr[4][4];
#pragma unroll
            for (int ng = 0; ng < 8; ng++) {
                uint32_t a01 = cvt_f16x2(e[ng][0] - m1, e[ng][1] - m1);
                uint32_t a23 = cvt_f16x2(e[ng][2] - m2, e[ng][3] - m2);
                uint32_t p01 = ex2h2(a01);
                uint32_t p23 = ex2h2(a23);
                int kp = ng >> 1;
                if ((ng & 1) == 0) { afr[kp][0] = p01; afr[kp][1] = p23; }
                else               { afr[kp][2] = p01; afr[kp][3] = p23; }
            }
            // z partial via HADD2 tree
            {
                uint32_t s1 = hadd2u(hadd2u(hadd2u(afr[0][0], afr[0][2]), hadd2u(afr[1][0], afr[1][2])),
                                     hadd2u(hadd2u(afr[2][0], afr[2][2]), hadd2u(afr[3][0], afr[3][2])));
                uint32_t s2 = hadd2u(hadd2u(hadd2u(afr[0][1], afr[0][3]), hadd2u(afr[1][1], afr[1][3])),
                                     hadd2u(hadd2u(afr[2][1], afr[2][3]), hadd2u(afr[3][1], afr[3][3])));
                float2 f1 = __half22float2(*(__half2*)&s1);
                float2 f2 = __half22float2(*(__half2*)&s2);
                z1 += f1.x + f1.y;
                z2 += f2.x + f2.y;
            }
            // accumulate mma (fp16)
#pragma unroll
            for (int ng2 = 0; ng2 < 4; ng2++) {
#pragma unroll
                for (int kp = 0; kp < 4; kp++) {
                    uint32_t off = fdrow + (uint32_t)(ng2*2048 + kp*32);
                    uint32_t f4[4];
                    ldsm_x4(f4[0], f4[1], f4[2], f4[3], sbase + buf*16384 + hs*8192 + SWZ(off));
                    mma_f16s(acc[2*ng2],   afr[kp], f4[0], f4[2]);
                    mma_f16s(acc[2*ng2+1], afr[kp], f4[1], f4[3]);
                }
            }
        }
    }
    // ---- z reduction across the quad ----
    z1 += __shfl_xor_sync(0xffffffffu, z1, 1);
    z1 += __shfl_xor_sync(0xffffffffu, z1, 2);
    z2 += __shfl_xor_sync(0xffffffffu, z2, 1);
    z2 += __shfl_xor_sync(0xffffffffu, z2, 2);
    if (tc == 0) {
        z_s[i1] = alpha_p[0] / z1;
        z_s[i2] = alpha_p[0] / z2;
    }
    __syncthreads();
    // ---- load psi tile / att / wp ----
    for (int idx = t; idx < 8192; idx += 256) {
        int c = idx >> 7, p = idx & 127;
        psi_s[c*132 + p] = d_psi[((size_t)b*Cn + c)*HWn + I0 + p];
    }
    for (int idx = t; idx < 4096; idx += 256)
        att_s[(idx >> 6)*65 + (idx & 63)] = d_att[b*4096 + idx];
    if (t < 64) wp_s[t] = d_wp[t];
    __syncthreads();
    // ---- CAM softmax -> W2_s[c][66] (4 threads per row) ----
    {
        int r = t >> 2, q4 = t & 3;
        float v[16];
#pragma unroll
        for (int k = 0; k < 16; k++) v[k] = att_s[r*65 + q4*16 + k];
        float mx = -1e30f, mn = 1e30f;
#pragma unroll
        for (int k = 0; k < 16; k++) { mx = fmaxf(mx, v[k]); mn = fminf(mn, v[k]); }
        mx = fmaxf(mx, __shfl_xor_sync(0xffffffffu, mx, 1));
        mx = fmaxf(mx, __shfl_xor_sync(0xffffffffu, mx, 2));
        mn = fminf(mn, __shfl_xor_sync(0xffffffffu, mn, 1));
        mn = fminf(mn, __shfl_xor_sync(0xffffffffu, mn, 2));
        float m2r = mx - mn;
        float ssum = 0.f;
#pragma unroll
        for (int k = 0; k < 16; k++) { float ev = __expf((mx - v[k]) - m2r); v[k] = ev; ssum += ev; }
        ssum += __shfl_xor_sync(0xffffffffu, ssum, 1);
        ssum += __shfl_xor_sync(0xffffffffu, ssum, 2);
        float scale = beta_p[0] * wp_s[r] / ssum;
#pragma unroll
        for (int k = 0; k < 16; k++) W2_s[r*66 + q4*16 + k] = v[k] * scale;
    }
    // ---- fragments -> pam_s[c][i] ----
    {
        float zz1 = z_s[i1], zz2 = z_s[i2];
#pragma unroll
        for (int ng = 0; ng < 8; ng++) {
            int c = ng*8 + 2*tc;
            pam_s[c*132 + i1]     = acc[ng][0]*zz1 + psi_s[c*132 + i1];
            pam_s[(c+1)*132 + i1] = acc[ng][1]*zz1 + psi_s[(c+1)*132 + i1];
            pam_s[c*132 + i2]     = acc[ng][2]*zz2 + psi_s[c*132 + i2];
            pam_s[(c+1)*132 + i2] = acc[ng][3]*zz2 + psi_s[(c+1)*132 + i2];
        }
    }
    __syncthreads();
    // ---- fused CAM + gate ----
    {
        int p = t & 127, half = t >> 7;
        int c0 = half*32, d0 = half*32;
        float part1 = 0.f;
#pragma unroll 8
        for (int c = 0; c < 32; c++) {
            int cc = c0 + c;
            part1 += wp_s[cc] * psi_s[cc*132 + p] * pam_s[cc*132 + p];
        }
        ull v[16];
#pragma unroll
        for (int q = 0; q < 16; q++) v[q] = 0ull;
        for (int c = 0; c < 64; c++) {
            float pm = pam_s[c*132 + p];
            ull pm2 = pk2(pm, pm);
            const ull* wr = (const ull*)&W2_s[c*66 + d0];
#pragma unroll
            for (int q = 0; q < 16; q++) v[q] = ffma2(pm2, wr[q], v[q]);
        }
        float part2 = 0.f;
#pragma unroll
        for (int q = 0; q < 16; q++) {
            float v0, v1; upk2(v[q], v0, v1);
            part2 += psi_s[(d0+2*q)*132 + p]*v0 + psi_s[(d0+2*q+1)*132 + p]*v1;
        }
        gred[half*128 + p] = part1 + part2;
    }
    __syncthreads();
    if (t < 128) {
        float gate = d_bp[0] + gred[t] + gred[128 + t];
        z_s[t] = 1.f / (1.f + __expf(-gate));   // da
    }
    __syncthreads();
    // ---- fused final multiply (float4 over positions) ----
    {
        int p4 = t & 31, c0 = t >> 5;
        float4 da = *(const float4*)&z_s[p4*4];
        const float* xp = x + ((size_t)b*256)*HWn + I0 + p4*4;
        float* op = out + ((size_t)b*256)*HWn + I0 + p4*4;
#pragma unroll 8
        for (int c = c0; c < 256; c += 8) {
            float4 v = *(const float4*)&xp[(size_t)c*HWn];
            v.x *= da.x; v.y *= da.y; v.z *= da.z; v.w *= da.w;
            *(float4*)&op[(size_t)c*HWn] = v;
        }
    }
}

// ---------------- launch ----------------
extern "C" void kernel_launch(void* const* d_in, const int* in_sizes, int n_in,
                              void* d_out, int out_size) {
    const float* g = (const float*)d_in[0];
    const float* x = (const float*)d_in[1];

    cudaFuncSetAttribute(k_psi2, cudaFuncAttributeMaxDynamicSharedMemorySize, 82176);
    cudaFuncSetAttribute(k_pam3, cudaFuncAttributeMaxDynamicSharedMemorySize, 102912);

    k_prep<<<128, 256>>>((const float*)d_in[2],  (const float*)d_in[3],  (const float*)d_in[4],
                        (const float*)d_in[5],  (const float*)d_in[6],  (const float*)d_in[7],
                        (const float*)d_in[8],  (const float*)d_in[9],  (const float*)d_in[10],
                        (const float*)d_in[11], (const float*)d_in[12], (const float*)d_in[13],
                        (const float*)d_in[14], (const float*)d_in[15], (const float*)d_in[16],
                        (const float*)d_in[17], (const float*)d_in[18], (const float*)d_in[19]);

    k_psi2<<<dim3(32, 8), 256, 82176>>>(g, x,
        (const float*)d_in[20], (const float*)d_in[21],
        (const float*)d_in[22], (const float*)d_in[23],
        (const float*)d_in[24], (const float*)d_in[25]);

    k_pam3<<<dim3(32, 8), 256, 102912>>>((const float*)d_in[26], (const float*)d_in[27],
                                         x, (float*)d_out);
}